// round 14
// baseline (speedup 1.0000x reference)
#include <cuda_runtime.h>
#include <math.h>
#include <stdint.h>

// ---------------- problem constants (fixed shapes) ----------------
// x: [8,256,96,96], means: [1,128,64], w_match: [64,256,3,3], b_match: [64]
// w_asm: [256,256,1,1], b_asm: [256]
// L = 9216, WINDOW = 144, n_win = 64, pad = 0, R = 1
//
// d_out layout (tuple concat, all f32):
//   out    [8,256,96,96]          @ 0
//   score  [8,1,64,144,432]       @ 18,874,368
//   bs     [8,1,9216]             @ 50,724,864
//   codes  [8,9216]               @ 50,798,592

#define NB   8
#define CIN  256
#define LTOK 9216
#define CQ   64
#define NCL  128
#define WIN  144
#define NWIN 64
#define WX3  432

// ---------------- device scratch ----------------
__device__ float g_xembed[NB*LTOK*CQ];     // conv3x3 out, token-major
__device__ float g_yembed[NB*LTOK*CIN];    // conv1x1 out, token-major
__device__ float g_inv[NB*LTOK];           // 1/max(||xembed_row||, 5e-5)
__device__ int   g_buckets[NB*LTOK];
__device__ int   g_counts[NB*NCL];
__device__ int   g_offs[NB*NCL];
__device__ int   g_idx[NB*LTOK];           // sorted pos -> token
__device__ int   g_undo[NB*LTOK];          // token -> sorted pos
__device__ float g_rets[NB*LTOK*CIN];      // attention output, sorted order

// ---------------- helpers ----------------
__device__ __forceinline__ uint32_t f2t(float f){
    uint32_t u; asm("cvt.rna.tf32.f32 %0, %1;" : "=r"(u) : "f"(f)); return u;
}
__device__ __forceinline__ void mma8(float c[4], uint32_t a0, uint32_t a1, uint32_t a2, uint32_t a3,
                                     uint32_t b0, uint32_t b1){
    asm volatile(
        "mma.sync.aligned.m16n8k8.row.col.f32.tf32.tf32.f32 "
        "{%0,%1,%2,%3}, {%4,%5,%6,%7}, {%8,%9}, {%0,%1,%2,%3};"
        : "+f"(c[0]), "+f"(c[1]), "+f"(c[2]), "+f"(c[3])
        : "r"(a0), "r"(a1), "r"(a2), "r"(a3), "r"(b0), "r"(b1));
}

// ---------------- conv 3x3, exact fp32 FFMA (at FFMA issue floor) ----------
__global__ __launch_bounds__(256) void k_conv3x3(const float* __restrict__ x,
                                                 const float* __restrict__ w,
                                                 const float* __restrict__ b) {
    __shared__ float in_s[8][3][100];   // 8 ch x 3 rows x cols(-1..96)
    __shared__ float w_s[8][9][64];
    int h = blockIdx.x, n = blockIdx.y;
    int tid = threadIdx.x;
    int cq = tid & 63, pg = tid >> 6;   // 4 groups x 24 positions
    float bias = b[cq];
    float acc[24];
#pragma unroll
    for (int p = 0; p < 24; p++) acc[p] = bias;

    for (int cc = 0; cc < 32; cc++) {   // 32 chunks of 8 input channels
        for (int i = tid; i < 8*3*98; i += 256) {
            int cl = i / 294, r = i % 294, kh = r / 98, col = r % 98;
            int hh = h + kh - 1, ww = col - 1;
            float v = 0.f;
            if (hh >= 0 && hh < 96 && ww >= 0 && ww < 96)
                v = x[((n*CIN + cc*8 + cl)*96 + hh)*96 + ww];
            in_s[cl][kh][col] = v;
        }
        for (int i = tid; i < 8*9*64; i += 256) {
            int cl = i / 576, r = i % 576, tap = r / 64, q = r & 63;
            w_s[cl][tap][q] = w[(q*CIN + cc*8 + cl)*9 + tap];
        }
        __syncthreads();
#pragma unroll
        for (int cl = 0; cl < 8; cl++) {
#pragma unroll
            for (int kh = 0; kh < 3; kh++) {
                float vin[26];
                {
                    const float4* vp = (const float4*)&in_s[cl][kh][pg*24];
#pragma unroll
                    for (int u = 0; u < 6; u++) {
                        float4 t = vp[u];
                        vin[4*u]   = t.x; vin[4*u+1] = t.y;
                        vin[4*u+2] = t.z; vin[4*u+3] = t.w;
                    }
                    float2 t2 = *(const float2*)&in_s[cl][kh][pg*24 + 24];
                    vin[24] = t2.x; vin[25] = t2.y;
                }
                float w0 = w_s[cl][kh*3+0][cq];
                float w1 = w_s[cl][kh*3+1][cq];
                float w2 = w_s[cl][kh*3+2][cq];
#pragma unroll
                for (int p = 0; p < 24; p++)
                    acc[p] += vin[p]*w0 + vin[p+1]*w1 + vin[p+2]*w2;
            }
        }
        __syncthreads();
    }
    int lbase = h*96 + pg*24;
#pragma unroll
    for (int p = 0; p < 24; p++)
        g_xembed[(n*LTOK + lbase + p)*CQ + cq] = acc[p];
}

// ---------------- conv 1x1 via tf32 mma, co-tile 64, 3 blocks/SM -----------
__global__ __launch_bounds__(256, 3) void k_conv1x1(const float* __restrict__ x,
                                                    const float* __restrict__ w,
                                                    const float* __restrict__ b) {
    __shared__ uint32_t As[128*36];  // A[l][k], k XOR-swizzled by (l>>3)&3
    __shared__ uint32_t Bs[64*36];   // B[n][k] (n-major), 64 channels
    int l0 = blockIdx.x*128, co0 = blockIdx.y*64, n = blockIdx.z;
    int tid = threadIdx.x, wid = tid >> 5, lane = tid & 31;
    int g = lane >> 2, tig = lane & 3;
    int m0 = wid * 16;
    float acc[8][4] = {};
    int c0x = (2*wid) & 3, c1x = (2*wid + 1) & 3;

    for (int kc = 0; kc < 8; kc++) {
        __syncthreads();
        for (int i = tid; i < 4096; i += 256) {
            int k = i >> 7, l = i & 127;
            float v = x[((size_t)(n*CIN + kc*32 + k))*LTOK + l0 + l];
            As[l*36 + (k ^ ((l >> 3) & 3))] = f2t(v);
        }
        for (int i = tid; i < 2048; i += 256) {
            int k = i & 31, j = i >> 5;
            float v = w[(co0 + j)*CIN + kc*32 + k];
            Bs[j*36 + k] = f2t(v);
        }
        __syncthreads();
#pragma unroll
        for (int ks = 0; ks < 4; ks++) {
            int kk = ks*8 + tig;
            uint32_t a0 = As[(m0+g  )*36 + ( kk    ^ c0x)];
            uint32_t a1 = As[(m0+g+8)*36 + ( kk    ^ c1x)];
            uint32_t a2 = As[(m0+g  )*36 + ((kk+4) ^ c0x)];
            uint32_t a3 = As[(m0+g+8)*36 + ((kk+4) ^ c1x)];
#pragma unroll
            for (int t = 0; t < 8; t++) {
                uint32_t b0 = Bs[(t*8+g)*36 + ks*8 + tig];
                uint32_t b1 = Bs[(t*8+g)*36 + ks*8 + tig + 4];
                mma8(acc[t], a0, a1, a2, a3, b0, b1);
            }
        }
    }
    int l = l0 + m0 + g;
#pragma unroll
    for (int t = 0; t < 8; t++) {
        int col = co0 + t*8 + 2*tig;
        float bb0 = b[col], bb1 = b[col+1];
        *(float2*)&g_yembed[((size_t)(n*LTOK + l    ))*CIN + col] =
            make_float2(acc[t][0] + bb0, acc[t][1] + bb1);
        *(float2*)&g_yembed[((size_t)(n*LTOK + l + 8))*CIN + col] =
            make_float2(acc[t][2] + bb0, acc[t][3] + bb1);
    }
}

// ---------------- bucket assignment + inv norm + fused histogram -----------
__global__ __launch_bounds__(128) void k_assign(const float* __restrict__ means,
                                                float* __restrict__ codes_out) {
    __shared__ float x_s[128][65];
    __shared__ float m_s[32][64];
    int n = blockIdx.y, t0 = blockIdx.x * 128, tid = threadIdx.x;
    for (int i = tid; i < 128*64; i += 128) {
        int r = i >> 6, c = i & 63;
        x_s[r][c] = g_xembed[(size_t)(n*LTOK + t0 + r)*CQ + c];
    }
    __syncthreads();
    {
        float ss = 0.f;
#pragma unroll
        for (int c = 0; c < 64; c++) { float v = x_s[tid][c]; ss += v*v; }
        g_inv[n*LTOK + t0 + tid] = 1.f / fmaxf(sqrtf(ss), 5e-5f);
    }
    float best = -INFINITY; int bk = 0;
    for (int kc = 0; kc < 4; kc++) {
        for (int i = tid; i < 32*64; i += 128) {
            int k = i >> 6, c = i & 63;
            m_s[k][c] = means[(kc*32 + k)*64 + c];
        }
        __syncthreads();
#pragma unroll
        for (int kg = 0; kg < 4; kg++) {
            float accv[8] = {};
            for (int c = 0; c < 64; c++) {
                float xv = x_s[tid][c];
#pragma unroll
                for (int e = 0; e < 8; e++) accv[e] += xv * m_s[kg*8+e][c];
            }
#pragma unroll
            for (int e = 0; e < 8; e++) {
                int k = kc*32 + kg*8 + e;
                if (accv[e] > best) { best = accv[e]; bk = k; }  // strict > = first-idx tie
            }
        }
        __syncthreads();
    }
    g_buckets[n*LTOK + t0 + tid] = bk;
    codes_out[n*LTOK + t0 + tid] = (float)bk;
    atomicAdd(&g_counts[n*NCL + bk], 1);   // fused histogram (was k_hist)
}

// ---------------- stable counting sort ------------------------------------
__global__ void k_histzero() {
    int i = blockIdx.x*256 + threadIdx.x;
    if (i < NB*NCL) g_counts[i] = 0;
}
__global__ void k_scan() {
    int n = blockIdx.x;
    if (threadIdx.x == 0) {
        int run = 0;
        for (int b2 = 0; b2 < NCL; b2++) { g_offs[n*NCL + b2] = run; run += g_counts[n*NCL + b2]; }
    }
}
__global__ __launch_bounds__(256) void k_place() {
    int g = blockIdx.x*8 + (threadIdx.x >> 5);
    int n = g >> 7, bkt = g & 127, lane = threadIdx.x & 31;
    int start = g_offs[n*NCL + bkt];
    int cnt = 0;
    const int* bk = &g_buckets[n*LTOK];
    for (int t0 = 0; t0 < LTOK; t0 += 32) {
        int t = t0 + lane;
        bool match = (bk[t] == bkt);
        unsigned m = __ballot_sync(0xffffffffu, match);
        if (match) {
            int pos = start + cnt + __popc(m & ((1u << lane) - 1u));
            g_idx[n*LTOK + pos] = t;
            g_undo[n*LTOK + t] = pos;
        }
        cnt += __popc(m);
    }
}

// ---------------- raw = xb @ xmatch^T (exact fp32; idx-indirect loads) ------
__global__ __launch_bounds__(256) void k_raw(float* __restrict__ score) {
    extern __shared__ float sm[];
    float* A = sm;                 // [144][69] sorted unnormalized
    float* B = sm + 144*69;        // [144][69] neighbor window normalized
    __shared__ int idxA[144], idxB[144];
    __shared__ float invB[144];
    int win = blockIdx.x, seg = blockIdx.y, n = blockIdx.z;
    int w2 = (seg == 0) ? win : (seg == 1) ? ((win + 63) & 63) : ((win + 1) & 63);
    int tid = threadIdx.x;
    for (int i = tid; i < 144; i += 256) {
        int ta = g_idx[n*LTOK + win*WIN + i];
        int tb = g_idx[n*LTOK + w2 *WIN + i];
        idxA[i] = ta; idxB[i] = tb;
        invB[i] = g_inv[n*LTOK + tb];
    }
    __syncthreads();
    for (int i = tid; i < 144*64; i += 256) {
        int r = i >> 6, k = i & 63;
        A[r*69 + k] = g_xembed[((size_t)(n*LTOK + idxA[r]))*CQ + k];
        B[r*69 + k] = g_xembed[((size_t)(n*LTOK + idxB[r]))*CQ + k] * invB[r];
    }
    __syncthreads();
    int ty = tid >> 4, tx = tid & 15;
    float acc[9][9] = {};
#pragma unroll 2
    for (int k = 0; k < 64; k++) {
        float av[9], bv[9];
#pragma unroll
        for (int u = 0; u < 9; u++) av[u] = A[(ty + 16*u)*69 + k];
#pragma unroll
        for (int v = 0; v < 9; v++) bv[v] = B[(tx + 16*v)*69 + k];
#pragma unroll
        for (int u = 0; u < 9; u++)
#pragma unroll
            for (int v = 0; v < 9; v++) acc[u][v] += av[u]*bv[v];
    }
    size_t base = (size_t)(n*NWIN + win) * WIN * WX3;
#pragma unroll
    for (int u = 0; u < 9; u++)
#pragma unroll
        for (int v = 0; v < 9; v++)
            score[base + (size_t)(ty + 16*u)*WX3 + seg*WIN + tx + 16*v] = acc[u][v];
}

// ---------------- logsumexp: single-exp rescale + __expf (PASSED R12/R13) --
__global__ __launch_bounds__(256) void k_lse(float* __restrict__ score,
                                             float* __restrict__ bsout) {
    int r = blockIdx.x*8 + (threadIdx.x >> 5);
    int lane = threadIdx.x & 31;
    float* p = score + (size_t)r * WX3;
    float v[14];
#pragma unroll
    for (int q = 0; q < 14; q++) {
        int j = q*32 + lane;
        v[q] = (j < WX3) ? p[j] : -INFINITY;
    }
    float m = -INFINITY;
#pragma unroll
    for (int q = 0; q < 14; q++) m = fmaxf(m, v[q]);
#pragma unroll
    for (int o = 16; o > 0; o >>= 1) m = fmaxf(m, __shfl_xor_sync(0xffffffffu, m, o));
    float e[14];
    float s = 0.f;
#pragma unroll
    for (int q = 0; q < 14; q++) { e[q] = __expf(v[q] - m); s += e[q]; }  // __expf(-inf)=0
#pragma unroll
    for (int o = 16; o > 0; o >>= 1) s += __shfl_xor_sync(0xffffffffu, s, o);
    float bs = m + logf(s);
    float rs = 1.f / s;
#pragma unroll
    for (int q = 0; q < 14; q++) {
        int j = q*32 + lane;
        if (j < WX3) p[j] = e[q] * rs;
    }
    if (lane == 0) bsout[r] = bs;
}

// ---------------- ret = score @ y3 via tf32 mma, co-tile 64, 3 blk/SM ------
__global__ __launch_bounds__(288, 3) void k_ret(const float* __restrict__ score) {
    extern __shared__ uint32_t dsm[];
    uint32_t* As = dsm;              // [144][52] tf32 score tile
    uint32_t* Bs = dsm + 144*52;     // [48][72] tf32 y tile (k-major, 64 ch + pad)
    __shared__ int idxs[432];
    int co0 = blockIdx.x*64, win = blockIdx.y, n = blockIdx.z;
    int tid = threadIdx.x, wid = tid >> 5, lane = tid & 31;
    int g = lane >> 2, tig = lane & 3;
    int m0 = wid * 16;
    for (int i = tid; i < 432; i += 288) {
        int seg = i / 144, off = i - seg*144;
        int w2 = (seg == 0) ? win : (seg == 1) ? ((win + 63) & 63) : ((win + 1) & 63);
        idxs[i] = g_idx[n*LTOK + w2*WIN + off];
    }
    float acc[8][4] = {};
    size_t sbase = ((size_t)(n*NWIN + win))*WIN*WX3;
    for (int kc = 0; kc < 9; kc++) {
        __syncthreads();
        for (int i = tid; i < 144*48; i += 288) {
            int r = i / 48, k = i - r*48;
            As[r*52 + k] = f2t(score[sbase + (size_t)r*WX3 + kc*48 + k]);
        }
        for (int i = tid; i < 48*64; i += 288) {
            int k = i >> 6, j = i & 63;
            int tok = idxs[kc*48 + k];
            Bs[k*72 + j] = f2t(g_yembed[((size_t)(n*LTOK + tok))*CIN + co0 + j]);
        }
        __syncthreads();
#pragma unroll
        for (int ks = 0; ks < 6; ks++) {
            uint32_t a0 = As[(m0+g  )*52 + ks*8 + tig];
            uint32_t a1 = As[(m0+g+8)*52 + ks*8 + tig];
            uint32_t a2 = As[(m0+g  )*52 + ks*8 + tig + 4];
            uint32_t a3 = As[(m0+g+8)*52 + ks*8 + tig + 4];
#pragma unroll
            for (int t = 0; t < 8; t++) {
                uint32_t b0 = Bs[(ks*8+tig  )*72 + t*8 + g];
                uint32_t b1 = Bs[(ks*8+tig+4)*72 + t*8 + g];
                mma8(acc[t], a0, a1, a2, a3, b0, b1);
            }
        }
    }
    int row = win*WIN + m0 + g;
#pragma unroll
    for (int t = 0; t < 8; t++) {
        int col = co0 + t*8 + 2*tig;
        *(float2*)&g_rets[((size_t)(n*LTOK + row    ))*CIN + col] = make_float2(acc[t][0], acc[t][1]);
        *(float2*)&g_rets[((size_t)(n*LTOK + row + 8))*CIN + col] = make_float2(acc[t][2], acc[t][3]);
    }
}

// ---------------- unsort + residual, coalesced via smem transpose ----------
__global__ __launch_bounds__(256) void k_scatter(const float* __restrict__ x,
                                                 float* __restrict__ out) {
    __shared__ float tile[32][257];
    __shared__ int srow[32];
    int n = blockIdx.y, t0 = blockIdx.x * 32, tid = threadIdx.x;
    if (tid < 32) srow[tid] = g_undo[n*LTOK + t0 + tid];
    __syncthreads();
    for (int i = tid; i < 32*256; i += 256) {
        int tt = i >> 8, co = i & 255;
        tile[tt][co] = g_rets[((size_t)(n*LTOK + srow[tt]))*CIN + co];
    }
    __syncthreads();
    for (int i = tid; i < 32*256; i += 256) {
        int co = i >> 5, tt = i & 31;
        size_t gi = ((size_t)(n*CIN + co))*LTOK + t0 + tt;
        out[gi] = tile[tt][co]*0.1f + x[gi];
    }
}

// ---------------- launch ----------------------------------------------------
// k_conv1x1 at launch slot 4 (profiler reports launch 4) to verify its
// occupancy fix next round. Fillers are idempotent histzero (3.7us each).
extern "C" void kernel_launch(void* const* d_in, const int* in_sizes, int n_in,
                              void* d_out, int out_size) {
    const float* x       = (const float*)d_in[0];
    const float* means   = (const float*)d_in[1];
    const float* w_match = (const float*)d_in[2];
    const float* b_match = (const float*)d_in[3];
    const float* w_asm   = (const float*)d_in[4];
    const float* b_asm   = (const float*)d_in[5];
    float* out   = (float*)d_out;
    float* score = out + 18874368;        // [8,1,64,144,432]
    float* bs    = out + 50724864;        // [8,1,9216]
    float* codes = out + 50798592;        // [8,9216]

    const int ret_smem = (144*52 + 48*72)*4;   // 43,776 B
    cudaFuncSetAttribute(k_raw, cudaFuncAttributeMaxDynamicSharedMemorySize, 2*144*69*4);
    cudaFuncSetAttribute(k_ret, cudaFuncAttributeMaxDynamicSharedMemorySize, ret_smem);

    k_histzero<<<4, 256>>>();                              // 1 (zeros counts)
    k_conv3x3<<<dim3(96, 8), 256>>>(x, w_match, b_match);  // 2
    k_histzero<<<4, 256>>>();                              // 3 (filler, idempotent)
    k_conv1x1<<<dim3(72, 4, 8), 256>>>(x, w_asm, b_asm);   // 4 <- profiled
    k_assign<<<dim3(72, 8), 128>>>(means, codes);          // 5 (assign + hist fused)
    k_scan<<<8, 32>>>();                                   // 6
    k_place<<<128, 256>>>();                               // 7
    k_raw<<<dim3(64, 3, 8), 256, 2*144*69*4>>>(score);     // 8
    k_lse<<<9216, 256>>>(score, bs);                       // 9
    k_ret<<<dim3(4, 64, 8), 288, ret_smem>>>(score);       // 10
    k_scatter<<<dim3(288, 8), 256>>>(x, out);              // 11
}

// round 16
// speedup vs baseline: 1.0872x; 1.0872x over previous
#include <cuda_runtime.h>
#include <math.h>
#include <stdint.h>

// ---------------- problem constants (fixed shapes) ----------------
// x: [8,256,96,96], means: [1,128,64], w_match: [64,256,3,3], b_match: [64]
// w_asm: [256,256,1,1], b_asm: [256]
// L = 9216, WINDOW = 144, n_win = 64, pad = 0, R = 1
//
// d_out layout (tuple concat, all f32):
//   out    [8,256,96,96]          @ 0
//   score  [8,1,64,144,432]       @ 18,874,368
//   bs     [8,1,9216]             @ 50,724,864
//   codes  [8,9216]               @ 50,798,592

#define NB   8
#define CIN  256
#define LTOK 9216
#define CQ   64
#define NCL  128
#define WIN  144
#define NWIN 64
#define WX3  432

// ---------------- device scratch ----------------
__device__ float g_xembed[NB*LTOK*CQ];     // conv3x3 out, token-major
__device__ float g_yembed[NB*LTOK*CIN];    // conv1x1 out, token-major
__device__ float g_inv[NB*LTOK];           // 1/max(||xembed_row||, 5e-5)
__device__ int   g_buckets[NB*LTOK];
__device__ int   g_counts[NB*NCL];
__device__ int   g_offs[NB*NCL];
__device__ int   g_idx[NB*LTOK];           // sorted pos -> token
__device__ int   g_undo[NB*LTOK];          // token -> sorted pos
__device__ float g_rets[NB*LTOK*CIN];      // attention output, sorted order

// ---------------- helpers ----------------
__device__ __forceinline__ uint32_t f2t(float f){
    uint32_t u; asm("cvt.rna.tf32.f32 %0, %1;" : "=r"(u) : "f"(f)); return u;
}
__device__ __forceinline__ void mma8(float c[4], uint32_t a0, uint32_t a1, uint32_t a2, uint32_t a3,
                                     uint32_t b0, uint32_t b1){
    asm volatile(
        "mma.sync.aligned.m16n8k8.row.col.f32.tf32.tf32.f32 "
        "{%0,%1,%2,%3}, {%4,%5,%6,%7}, {%8,%9}, {%0,%1,%2,%3};"
        : "+f"(c[0]), "+f"(c[1]), "+f"(c[2]), "+f"(c[3])
        : "r"(a0), "r"(a1), "r"(a2), "r"(a3), "r"(b0), "r"(b1));
}

// ---------------- conv 3x3, exact fp32 FFMA (at FFMA issue floor) ----------
__global__ __launch_bounds__(256) void k_conv3x3(const float* __restrict__ x,
                                                 const float* __restrict__ w,
                                                 const float* __restrict__ b) {
    __shared__ float in_s[8][3][100];   // 8 ch x 3 rows x cols(-1..96)
    __shared__ float w_s[8][9][64];
    int h = blockIdx.x, n = blockIdx.y;
    int tid = threadIdx.x;
    int cq = tid & 63, pg = tid >> 6;   // 4 groups x 24 positions
    float bias = b[cq];
    float acc[24];
#pragma unroll
    for (int p = 0; p < 24; p++) acc[p] = bias;

    for (int cc = 0; cc < 32; cc++) {   // 32 chunks of 8 input channels
        for (int i = tid; i < 8*3*98; i += 256) {
            int cl = i / 294, r = i % 294, kh = r / 98, col = r % 98;
            int hh = h + kh - 1, ww = col - 1;
            float v = 0.f;
            if (hh >= 0 && hh < 96 && ww >= 0 && ww < 96)
                v = x[((n*CIN + cc*8 + cl)*96 + hh)*96 + ww];
            in_s[cl][kh][col] = v;
        }
        for (int i = tid; i < 8*9*64; i += 256) {
            int cl = i / 576, r = i % 576, tap = r / 64, q = r & 63;
            w_s[cl][tap][q] = w[(q*CIN + cc*8 + cl)*9 + tap];
        }
        __syncthreads();
#pragma unroll
        for (int cl = 0; cl < 8; cl++) {
#pragma unroll
            for (int kh = 0; kh < 3; kh++) {
                float vin[26];
                {
                    const float4* vp = (const float4*)&in_s[cl][kh][pg*24];
#pragma unroll
                    for (int u = 0; u < 6; u++) {
                        float4 t = vp[u];
                        vin[4*u]   = t.x; vin[4*u+1] = t.y;
                        vin[4*u+2] = t.z; vin[4*u+3] = t.w;
                    }
                    float2 t2 = *(const float2*)&in_s[cl][kh][pg*24 + 24];
                    vin[24] = t2.x; vin[25] = t2.y;
                }
                float w0 = w_s[cl][kh*3+0][cq];
                float w1 = w_s[cl][kh*3+1][cq];
                float w2 = w_s[cl][kh*3+2][cq];
#pragma unroll
                for (int p = 0; p < 24; p++)
                    acc[p] += vin[p]*w0 + vin[p+1]*w1 + vin[p+2]*w2;
            }
        }
        __syncthreads();
    }
    int lbase = h*96 + pg*24;
#pragma unroll
    for (int p = 0; p < 24; p++)
        g_xembed[(n*LTOK + lbase + p)*CQ + cq] = acc[p];
}

// ---------------- conv 1x1 via tf32 mma, co-tile 64, 3 blocks/SM -----------
// (measured R14: 173us, regs=80 < 85 cap, no spills — keep)
__global__ __launch_bounds__(256, 3) void k_conv1x1(const float* __restrict__ x,
                                                    const float* __restrict__ w,
                                                    const float* __restrict__ b) {
    __shared__ uint32_t As[128*36];  // A[l][k], k XOR-swizzled by (l>>3)&3
    __shared__ uint32_t Bs[64*36];   // B[n][k] (n-major), 64 channels
    int l0 = blockIdx.x*128, co0 = blockIdx.y*64, n = blockIdx.z;
    int tid = threadIdx.x, wid = tid >> 5, lane = tid & 31;
    int g = lane >> 2, tig = lane & 3;
    int m0 = wid * 16;
    float acc[8][4] = {};
    int c0x = (2*wid) & 3, c1x = (2*wid + 1) & 3;

    for (int kc = 0; kc < 8; kc++) {
        __syncthreads();
        for (int i = tid; i < 4096; i += 256) {
            int k = i >> 7, l = i & 127;
            float v = x[((size_t)(n*CIN + kc*32 + k))*LTOK + l0 + l];
            As[l*36 + (k ^ ((l >> 3) & 3))] = f2t(v);
        }
        for (int i = tid; i < 2048; i += 256) {
            int k = i & 31, j = i >> 5;
            float v = w[(co0 + j)*CIN + kc*32 + k];
            Bs[j*36 + k] = f2t(v);
        }
        __syncthreads();
#pragma unroll
        for (int ks = 0; ks < 4; ks++) {
            int kk = ks*8 + tig;
            uint32_t a0 = As[(m0+g  )*36 + ( kk    ^ c0x)];
            uint32_t a1 = As[(m0+g+8)*36 + ( kk    ^ c1x)];
            uint32_t a2 = As[(m0+g  )*36 + ((kk+4) ^ c0x)];
            uint32_t a3 = As[(m0+g+8)*36 + ((kk+4) ^ c1x)];
#pragma unroll
            for (int t = 0; t < 8; t++) {
                uint32_t b0 = Bs[(t*8+g)*36 + ks*8 + tig];
                uint32_t b1 = Bs[(t*8+g)*36 + ks*8 + tig + 4];
                mma8(acc[t], a0, a1, a2, a3, b0, b1);
            }
        }
    }
    int l = l0 + m0 + g;
#pragma unroll
    for (int t = 0; t < 8; t++) {
        int col = co0 + t*8 + 2*tig;
        float bb0 = b[col], bb1 = b[col+1];
        *(float2*)&g_yembed[((size_t)(n*LTOK + l    ))*CIN + col] =
            make_float2(acc[t][0] + bb0, acc[t][1] + bb1);
        *(float2*)&g_yembed[((size_t)(n*LTOK + l + 8))*CIN + col] =
            make_float2(acc[t][2] + bb0, acc[t][3] + bb1);
    }
}

// ---------------- bucket assignment + inv norm + fused histogram -----------
__global__ __launch_bounds__(128) void k_assign(const float* __restrict__ means,
                                                float* __restrict__ codes_out) {
    __shared__ float x_s[128][65];
    __shared__ float m_s[32][64];
    int n = blockIdx.y, t0 = blockIdx.x * 128, tid = threadIdx.x;
    for (int i = tid; i < 128*64; i += 128) {
        int r = i >> 6, c = i & 63;
        x_s[r][c] = g_xembed[(size_t)(n*LTOK + t0 + r)*CQ + c];
    }
    __syncthreads();
    {
        float ss = 0.f;
#pragma unroll
        for (int c = 0; c < 64; c++) { float v = x_s[tid][c]; ss += v*v; }
        g_inv[n*LTOK + t0 + tid] = 1.f / fmaxf(sqrtf(ss), 5e-5f);
    }
    float best = -INFINITY; int bk = 0;
    for (int kc = 0; kc < 4; kc++) {
        for (int i = tid; i < 32*64; i += 128) {
            int k = i >> 6, c = i & 63;
            m_s[k][c] = means[(kc*32 + k)*64 + c];
        }
        __syncthreads();
#pragma unroll
        for (int kg = 0; kg < 4; kg++) {
            float accv[8] = {};
            for (int c = 0; c < 64; c++) {
                float xv = x_s[tid][c];
#pragma unroll
                for (int e = 0; e < 8; e++) accv[e] += xv * m_s[kg*8+e][c];
            }
#pragma unroll
            for (int e = 0; e < 8; e++) {
                int k = kc*32 + kg*8 + e;
                if (accv[e] > best) { best = accv[e]; bk = k; }  // strict > = first-idx tie
            }
        }
        __syncthreads();
    }
    g_buckets[n*LTOK + t0 + tid] = bk;
    codes_out[n*LTOK + t0 + tid] = (float)bk;
    atomicAdd(&g_counts[n*NCL + bk], 1);   // fused histogram
}

// ---------------- stable counting sort ------------------------------------
__global__ void k_histzero() {
    int i = blockIdx.x*256 + threadIdx.x;
    if (i < NB*NCL) g_counts[i] = 0;
}
__global__ void k_scan() {
    int n = blockIdx.x;
    if (threadIdx.x == 0) {
        int run = 0;
        for (int b2 = 0; b2 < NCL; b2++) { g_offs[n*NCL + b2] = run; run += g_counts[n*NCL + b2]; }
    }
}
__global__ __launch_bounds__(256) void k_place() {
    int g = blockIdx.x*8 + (threadIdx.x >> 5);
    int n = g >> 7, bkt = g & 127, lane = threadIdx.x & 31;
    int start = g_offs[n*NCL + bkt];
    int cnt = 0;
    const int* bk = &g_buckets[n*LTOK];
    for (int t0 = 0; t0 < LTOK; t0 += 32) {
        int t = t0 + lane;
        bool match = (bk[t] == bkt);
        unsigned m = __ballot_sync(0xffffffffu, match);
        if (match) {
            int pos = start + cnt + __popc(m & ((1u << lane) - 1u));
            g_idx[n*LTOK + pos] = t;
            g_undo[n*LTOK + t] = pos;
        }
        cnt += __popc(m);
    }
}

// ---------------- raw = xb @ xmatch^T (exact fp32; idx-indirect loads) ------
__global__ __launch_bounds__(256) void k_raw(float* __restrict__ score) {
    extern __shared__ float sm[];
    float* A = sm;                 // [144][69] sorted unnormalized
    float* B = sm + 144*69;        // [144][69] neighbor window normalized
    __shared__ int idxA[144], idxB[144];
    __shared__ float invB[144];
    int win = blockIdx.x, seg = blockIdx.y, n = blockIdx.z;
    int w2 = (seg == 0) ? win : (seg == 1) ? ((win + 63) & 63) : ((win + 1) & 63);
    int tid = threadIdx.x;
    for (int i = tid; i < 144; i += 256) {
        int ta = g_idx[n*LTOK + win*WIN + i];
        int tb = g_idx[n*LTOK + w2 *WIN + i];
        idxA[i] = ta; idxB[i] = tb;
        invB[i] = g_inv[n*LTOK + tb];
    }
    __syncthreads();
    for (int i = tid; i < 144*64; i += 256) {
        int r = i >> 6, k = i & 63;
        A[r*69 + k] = g_xembed[((size_t)(n*LTOK + idxA[r]))*CQ + k];
        B[r*69 + k] = g_xembed[((size_t)(n*LTOK + idxB[r]))*CQ + k] * invB[r];
    }
    __syncthreads();
    int ty = tid >> 4, tx = tid & 15;
    float acc[9][9] = {};
#pragma unroll 2
    for (int k = 0; k < 64; k++) {
        float av[9], bv[9];
#pragma unroll
        for (int u = 0; u < 9; u++) av[u] = A[(ty + 16*u)*69 + k];
#pragma unroll
        for (int v = 0; v < 9; v++) bv[v] = B[(tx + 16*v)*69 + k];
#pragma unroll
        for (int u = 0; u < 9; u++)
#pragma unroll
            for (int v = 0; v < 9; v++) acc[u][v] += av[u]*bv[v];
    }
    size_t base = (size_t)(n*NWIN + win) * WIN * WX3;
#pragma unroll
    for (int u = 0; u < 9; u++)
#pragma unroll
        for (int v = 0; v < 9; v++)
            score[base + (size_t)(ty + 16*u)*WX3 + seg*WIN + tx + 16*v] = acc[u][v];
}

// ---------------- logsumexp: single-exp rescale + __expf (PASSED R12/R13) --
__global__ __launch_bounds__(256) void k_lse(float* __restrict__ score,
                                             float* __restrict__ bsout) {
    int r = blockIdx.x*8 + (threadIdx.x >> 5);
    int lane = threadIdx.x & 31;
    float* p = score + (size_t)r * WX3;
    float v[14];
#pragma unroll
    for (int q = 0; q < 14; q++) {
        int j = q*32 + lane;
        v[q] = (j < WX3) ? p[j] : -INFINITY;
    }
    float m = -INFINITY;
#pragma unroll
    for (int q = 0; q < 14; q++) m = fmaxf(m, v[q]);
#pragma unroll
    for (int o = 16; o > 0; o >>= 1) m = fmaxf(m, __shfl_xor_sync(0xffffffffu, m, o));
    float e[14];
    float s = 0.f;
#pragma unroll
    for (int q = 0; q < 14; q++) { e[q] = __expf(v[q] - m); s += e[q]; }  // __expf(-inf)=0
#pragma unroll
    for (int o = 16; o > 0; o >>= 1) s += __shfl_xor_sync(0xffffffffu, s, o);
    float bs = m + logf(s);
    float rs = 1.f / s;
#pragma unroll
    for (int q = 0; q < 14; q++) {
        int j = q*32 + lane;
        if (j < WX3) p[j] = e[q] * rs;
    }
    if (lane == 0) bsout[r] = bs;
}

// ---------------- ret = score @ y3 via tf32 mma, co-tile 64, 2 blk/SM ------
// REVERTED to (288,2): the (288,3) cap of 75 regs forced spills (+105us R14).
__global__ __launch_bounds__(288, 2) void k_ret(const float* __restrict__ score) {
    extern __shared__ uint32_t dsm[];
    uint32_t* As = dsm;              // [144][52] tf32 score tile
    uint32_t* Bs = dsm + 144*52;     // [48][72] tf32 y tile (k-major, 64 ch + pad)
    __shared__ int idxs[432];
    int co0 = blockIdx.x*64, win = blockIdx.y, n = blockIdx.z;
    int tid = threadIdx.x, wid = tid >> 5, lane = tid & 31;
    int g = lane >> 2, tig = lane & 3;
    int m0 = wid * 16;
    for (int i = tid; i < 432; i += 288) {
        int seg = i / 144, off = i - seg*144;
        int w2 = (seg == 0) ? win : (seg == 1) ? ((win + 63) & 63) : ((win + 1) & 63);
        idxs[i] = g_idx[n*LTOK + w2*WIN + off];
    }
    float acc[8][4] = {};
    size_t sbase = ((size_t)(n*NWIN + win))*WIN*WX3;
    for (int kc = 0; kc < 9; kc++) {
        __syncthreads();
        for (int i = tid; i < 144*48; i += 288) {
            int r = i / 48, k = i - r*48;
            As[r*52 + k] = f2t(score[sbase + (size_t)r*WX3 + kc*48 + k]);
        }
        for (int i = tid; i < 48*64; i += 288) {
            int k = i >> 6, j = i & 63;
            int tok = idxs[kc*48 + k];
            Bs[k*72 + j] = f2t(g_yembed[((size_t)(n*LTOK + tok))*CIN + co0 + j]);
        }
        __syncthreads();
#pragma unroll
        for (int ks = 0; ks < 6; ks++) {
            uint32_t a0 = As[(m0+g  )*52 + ks*8 + tig];
            uint32_t a1 = As[(m0+g+8)*52 + ks*8 + tig];
            uint32_t a2 = As[(m0+g  )*52 + ks*8 + tig + 4];
            uint32_t a3 = As[(m0+g+8)*52 + ks*8 + tig + 4];
#pragma unroll
            for (int t = 0; t < 8; t++) {
                uint32_t b0 = Bs[(ks*8+tig  )*72 + t*8 + g];
                uint32_t b1 = Bs[(ks*8+tig+4)*72 + t*8 + g];
                mma8(acc[t], a0, a1, a2, a3, b0, b1);
            }
        }
    }
    int row = win*WIN + m0 + g;
#pragma unroll
    for (int t = 0; t < 8; t++) {
        int col = co0 + t*8 + 2*tig;
        *(float2*)&g_rets[((size_t)(n*LTOK + row    ))*CIN + col] = make_float2(acc[t][0], acc[t][1]);
        *(float2*)&g_rets[((size_t)(n*LTOK + row + 8))*CIN + col] = make_float2(acc[t][2], acc[t][3]);
    }
}

// ---------------- unsort + residual, coalesced via smem transpose ----------
__global__ __launch_bounds__(256) void k_scatter(const float* __restrict__ x,
                                                 float* __restrict__ out) {
    __shared__ float tile[32][257];
    __shared__ int srow[32];
    int n = blockIdx.y, t0 = blockIdx.x * 32, tid = threadIdx.x;
    if (tid < 32) srow[tid] = g_undo[n*LTOK + t0 + tid];
    __syncthreads();
    for (int i = tid; i < 32*64; i += 256) {
        int tt = i >> 6, co4 = (i & 63)*4;
        float4 v = *(const float4*)&g_rets[((size_t)(n*LTOK + srow[tt]))*CIN + co4];
        tile[tt][co4]   = v.x; tile[tt][co4+1] = v.y;
        tile[tt][co4+2] = v.z; tile[tt][co4+3] = v.w;
    }
    __syncthreads();
    for (int i = tid; i < 32*256; i += 256) {
        int co = i >> 5, tt = i & 31;
        size_t gi = ((size_t)(n*CIN + co))*LTOK + t0 + tt;
        out[gi] = tile[tt][co]*0.1f + x[gi];
    }
}

// ---------------- launch ----------------------------------------------------
extern "C" void kernel_launch(void* const* d_in, const int* in_sizes, int n_in,
                              void* d_out, int out_size) {
    const float* x       = (const float*)d_in[0];
    const float* means   = (const float*)d_in[1];
    const float* w_match = (const float*)d_in[2];
    const float* b_match = (const float*)d_in[3];
    const float* w_asm   = (const float*)d_in[4];
    const float* b_asm   = (const float*)d_in[5];
    float* out   = (float*)d_out;
    float* score = out + 18874368;        // [8,1,64,144,432]
    float* bs    = out + 50724864;        // [8,1,9216]
    float* codes = out + 50798592;        // [8,9216]

    const int ret_smem = (144*52 + 48*72)*4;   // 43,776 B
    cudaFuncSetAttribute(k_raw, cudaFuncAttributeMaxDynamicSharedMemorySize, 2*144*69*4);
    cudaFuncSetAttribute(k_ret, cudaFuncAttributeMaxDynamicSharedMemorySize, ret_smem);

    k_histzero<<<4, 256>>>();                              // 1 (zeros counts)
    k_conv3x3<<<dim3(96, 8), 256>>>(x, w_match, b_match);  // 2
    k_histzero<<<4, 256>>>();                              // 3 (filler, idempotent)
    k_conv1x1<<<dim3(72, 4, 8), 256>>>(x, w_asm, b_asm);   // 4 <- profiled
    k_assign<<<dim3(72, 8), 128>>>(means, codes);          // 5 (assign + hist fused)
    k_scan<<<8, 32>>>();                                   // 6
    k_place<<<128, 256>>>();                               // 7
    k_raw<<<dim3(64, 3, 8), 256, 2*144*69*4>>>(score);     // 8
    k_lse<<<9216, 256>>>(score, bs);                       // 9
    k_ret<<<dim3(4, 64, 8), 288, ret_smem>>>(score);       // 10
    k_scatter<<<dim3(288, 8), 256>>>(x, out);              // 11
}

// round 17
// speedup vs baseline: 1.2428x; 1.1431x over previous
#include <cuda_runtime.h>
#include <cuda_fp16.h>
#include <math.h>
#include <stdint.h>

// ---------------- problem constants (fixed shapes) ----------------
#define NB   8
#define CIN  256
#define LTOK 9216
#define CQ   64
#define NCL  128
#define WIN  144
#define NWIN 64
#define WX3  432

// ---------------- device scratch ----------------
__device__ float g_xembed[NB*LTOK*CQ];
__device__ float g_yembed[NB*LTOK*CIN];
__device__ float g_inv[NB*LTOK];
__device__ int   g_buckets[NB*LTOK];
__device__ int   g_counts[NB*NCL];
__device__ int   g_offs[NB*NCL];
__device__ int   g_idx[NB*LTOK];
__device__ int   g_undo[NB*LTOK];
__device__ float g_rets[NB*LTOK*CIN];

// ---------------- helpers ----------------
__device__ __forceinline__ uint32_t pkh2(float lo, float hi){
    __half2 h = __floats2half2_rn(lo, hi);   // .x = lo -> low 16 bits
    return *(uint32_t*)&h;
}
__device__ __forceinline__ void mma16(float c[4], uint32_t a0, uint32_t a1, uint32_t a2, uint32_t a3,
                                      uint32_t b0, uint32_t b1){
    asm volatile(
        "mma.sync.aligned.m16n8k16.row.col.f32.f16.f16.f32 "
        "{%0,%1,%2,%3}, {%4,%5,%6,%7}, {%8,%9}, {%0,%1,%2,%3};"
        : "+f"(c[0]), "+f"(c[1]), "+f"(c[2]), "+f"(c[3])
        : "r"(a0), "r"(a1), "r"(a2), "r"(a3), "r"(b0), "r"(b1));
}

// ---------------- conv 3x3, exact fp32 FFMA (pipe-saturated; parked) -------
__global__ __launch_bounds__(256) void k_conv3x3(const float* __restrict__ x,
                                                 const float* __restrict__ w,
                                                 const float* __restrict__ b) {
    __shared__ float in_s[8][3][100];
    __shared__ float w_s[8][9][64];
    int h = blockIdx.x, n = blockIdx.y;
    int tid = threadIdx.x;
    int cq = tid & 63, pg = tid >> 6;
    float bias = b[cq];
    float acc[24];
#pragma unroll
    for (int p = 0; p < 24; p++) acc[p] = bias;

    for (int cc = 0; cc < 32; cc++) {
        for (int i = tid; i < 8*3*98; i += 256) {
            int cl = i / 294, r = i % 294, kh = r / 98, col = r % 98;
            int hh = h + kh - 1, ww = col - 1;
            float v = 0.f;
            if (hh >= 0 && hh < 96 && ww >= 0 && ww < 96)
                v = x[((n*CIN + cc*8 + cl)*96 + hh)*96 + ww];
            in_s[cl][kh][col] = v;
        }
        for (int i = tid; i < 8*9*64; i += 256) {
            int cl = i / 576, r = i % 576, tap = r / 64, q = r & 63;
            w_s[cl][tap][q] = w[(q*CIN + cc*8 + cl)*9 + tap];
        }
        __syncthreads();
#pragma unroll
        for (int cl = 0; cl < 8; cl++) {
#pragma unroll
            for (int kh = 0; kh < 3; kh++) {
                float vin[26];
                {
                    const float4* vp = (const float4*)&in_s[cl][kh][pg*24];
#pragma unroll
                    for (int u = 0; u < 6; u++) {
                        float4 t = vp[u];
                        vin[4*u]   = t.x; vin[4*u+1] = t.y;
                        vin[4*u+2] = t.z; vin[4*u+3] = t.w;
                    }
                    float2 t2 = *(const float2*)&in_s[cl][kh][pg*24 + 24];
                    vin[24] = t2.x; vin[25] = t2.y;
                }
                float w0 = w_s[cl][kh*3+0][cq];
                float w1 = w_s[cl][kh*3+1][cq];
                float w2 = w_s[cl][kh*3+2][cq];
#pragma unroll
                for (int p = 0; p < 24; p++)
                    acc[p] += vin[p]*w0 + vin[p+1]*w1 + vin[p+2]*w2;
            }
        }
        __syncthreads();
    }
    int lbase = h*96 + pg*24;
#pragma unroll
    for (int p = 0; p < 24; p++)
        g_xembed[(n*LTOK + lbase + p)*CQ + cq] = acc[p];
}

// ---------------- conv 1x1 via fp16 mma (m16n8k16), co-tile 64, 3 blk/SM ---
// fp16 mantissa = 10 bits = tf32 mantissa: same rounding error as the
// PASSED tf32 version, half the mma instructions.
__global__ __launch_bounds__(256, 3) void k_conv1x1(const float* __restrict__ x,
                                                    const float* __restrict__ w,
                                                    const float* __restrict__ b) {
    __shared__ uint32_t As2[128*20];  // [l][k2], k2<16 (half2 pairs along k), pad 20
    __shared__ uint32_t Bs2[64*20];   // [j][k2]
    int l0 = blockIdx.x*128, co0 = blockIdx.y*64, n = blockIdx.z;
    int tid = threadIdx.x, wid = tid >> 5, lane = tid & 31;
    int g = lane >> 2, tig = lane & 3;
    int m0 = wid * 16;
    float acc[8][4] = {};

    for (int kc = 0; kc < 8; kc++) {
        __syncthreads();
        for (int i = tid; i < 2048; i += 256) {
            int k2 = i >> 7, l = i & 127;
            float v0 = x[((size_t)(n*CIN + kc*32 + 2*k2    ))*LTOK + l0 + l];
            float v1 = x[((size_t)(n*CIN + kc*32 + 2*k2 + 1))*LTOK + l0 + l];
            As2[l*20 + k2] = pkh2(v0, v1);
        }
        for (int i = tid; i < 1024; i += 256) {
            int j = i >> 4, k2 = i & 15;
            float2 v = *(const float2*)&w[(co0 + j)*CIN + kc*32 + 2*k2];
            Bs2[j*20 + k2] = pkh2(v.x, v.y);
        }
        __syncthreads();
#pragma unroll
        for (int s = 0; s < 2; s++) {
            uint32_t a0 = As2[(m0+g  )*20 + s*8 + tig];
            uint32_t a1 = As2[(m0+g+8)*20 + s*8 + tig];
            uint32_t a2 = As2[(m0+g  )*20 + s*8 + tig + 4];
            uint32_t a3 = As2[(m0+g+8)*20 + s*8 + tig + 4];
#pragma unroll
            for (int t = 0; t < 8; t++) {
                uint32_t b0 = Bs2[(t*8+g)*20 + s*8 + tig];
                uint32_t b1 = Bs2[(t*8+g)*20 + s*8 + tig + 4];
                mma16(acc[t], a0, a1, a2, a3, b0, b1);
            }
        }
    }
    int l = l0 + m0 + g;
#pragma unroll
    for (int t = 0; t < 8; t++) {
        int col = co0 + t*8 + 2*tig;
        float bb0 = b[col], bb1 = b[col+1];
        *(float2*)&g_yembed[((size_t)(n*LTOK + l    ))*CIN + col] =
            make_float2(acc[t][0] + bb0, acc[t][1] + bb1);
        *(float2*)&g_yembed[((size_t)(n*LTOK + l + 8))*CIN + col] =
            make_float2(acc[t][2] + bb0, acc[t][3] + bb1);
    }
}

// ---------------- bucket assignment + inv norm + fused histogram -----------
__global__ __launch_bounds__(128) void k_assign(const float* __restrict__ means,
                                                float* __restrict__ codes_out) {
    __shared__ float x_s[128][65];
    __shared__ float m_s[32][64];
    int n = blockIdx.y, t0 = blockIdx.x * 128, tid = threadIdx.x;
    for (int i = tid; i < 128*64; i += 128) {
        int r = i >> 6, c = i & 63;
        x_s[r][c] = g_xembed[(size_t)(n*LTOK + t0 + r)*CQ + c];
    }
    __syncthreads();
    {
        float ss = 0.f;
#pragma unroll
        for (int c = 0; c < 64; c++) { float v = x_s[tid][c]; ss += v*v; }
        g_inv[n*LTOK + t0 + tid] = 1.f / fmaxf(sqrtf(ss), 5e-5f);
    }
    float best = -INFINITY; int bk = 0;
    for (int kc = 0; kc < 4; kc++) {
        for (int i = tid; i < 32*64; i += 128) {
            int k = i >> 6, c = i & 63;
            m_s[k][c] = means[(kc*32 + k)*64 + c];
        }
        __syncthreads();
#pragma unroll
        for (int kg = 0; kg < 4; kg++) {
            float accv[8] = {};
            for (int c = 0; c < 64; c++) {
                float xv = x_s[tid][c];
#pragma unroll
                for (int e = 0; e < 8; e++) accv[e] += xv * m_s[kg*8+e][c];
            }
#pragma unroll
            for (int e = 0; e < 8; e++) {
                int k = kc*32 + kg*8 + e;
                if (accv[e] > best) { best = accv[e]; bk = k; }
            }
        }
        __syncthreads();
    }
    g_buckets[n*LTOK + t0 + tid] = bk;
    codes_out[n*LTOK + t0 + tid] = (float)bk;
    atomicAdd(&g_counts[n*NCL + bk], 1);
}

// ---------------- stable counting sort ------------------------------------
__global__ void k_histzero() {
    int i = blockIdx.x*256 + threadIdx.x;
    if (i < NB*NCL) g_counts[i] = 0;
}
__global__ void k_scan() {
    int n = blockIdx.x;
    if (threadIdx.x == 0) {
        int run = 0;
        for (int b2 = 0; b2 < NCL; b2++) { g_offs[n*NCL + b2] = run; run += g_counts[n*NCL + b2]; }
    }
}
__global__ __launch_bounds__(256) void k_place() {
    int g = blockIdx.x*8 + (threadIdx.x >> 5);
    int n = g >> 7, bkt = g & 127, lane = threadIdx.x & 31;
    int start = g_offs[n*NCL + bkt];
    int cnt = 0;
    const int* bk = &g_buckets[n*LTOK];
    for (int t0 = 0; t0 < LTOK; t0 += 32) {
        int t = t0 + lane;
        bool match = (bk[t] == bkt);
        unsigned m = __ballot_sync(0xffffffffu, match);
        if (match) {
            int pos = start + cnt + __popc(m & ((1u << lane) - 1u));
            g_idx[n*LTOK + pos] = t;
            g_undo[n*LTOK + t] = pos;
        }
        cnt += __popc(m);
    }
}

// ---------------- raw = xb @ xmatch^T (exact fp32; idx-indirect loads) ------
__global__ __launch_bounds__(256) void k_raw(float* __restrict__ score) {
    extern __shared__ float sm[];
    float* A = sm;                 // [144][69]
    float* B = sm + 144*69;        // [144][69]
    __shared__ int idxA[144], idxB[144];
    __shared__ float invB[144];
    int win = blockIdx.x, seg = blockIdx.y, n = blockIdx.z;
    int w2 = (seg == 0) ? win : (seg == 1) ? ((win + 63) & 63) : ((win + 1) & 63);
    int tid = threadIdx.x;
    for (int i = tid; i < 144; i += 256) {
        int ta = g_idx[n*LTOK + win*WIN + i];
        int tb = g_idx[n*LTOK + w2 *WIN + i];
        idxA[i] = ta; idxB[i] = tb;
        invB[i] = g_inv[n*LTOK + tb];
    }
    __syncthreads();
    for (int i = tid; i < 144*64; i += 256) {
        int r = i >> 6, k = i & 63;
        A[r*69 + k] = g_xembed[((size_t)(n*LTOK + idxA[r]))*CQ + k];
        B[r*69 + k] = g_xembed[((size_t)(n*LTOK + idxB[r]))*CQ + k] * invB[r];
    }
    __syncthreads();
    int ty = tid >> 4, tx = tid & 15;
    float acc[9][9] = {};
#pragma unroll 2
    for (int k = 0; k < 64; k++) {
        float av[9], bv[9];
#pragma unroll
        for (int u = 0; u < 9; u++) av[u] = A[(ty + 16*u)*69 + k];
#pragma unroll
        for (int v = 0; v < 9; v++) bv[v] = B[(tx + 16*v)*69 + k];
#pragma unroll
        for (int u = 0; u < 9; u++)
#pragma unroll
            for (int v = 0; v < 9; v++) acc[u][v] += av[u]*bv[v];
    }
    size_t base = (size_t)(n*NWIN + win) * WIN * WX3;
#pragma unroll
    for (int u = 0; u < 9; u++)
#pragma unroll
        for (int v = 0; v < 9; v++)
            score[base + (size_t)(ty + 16*u)*WX3 + seg*WIN + tx + 16*v] = acc[u][v];
}

// ---------------- logsumexp: single-exp rescale + __expf -------------------
__global__ __launch_bounds__(256) void k_lse(float* __restrict__ score,
                                             float* __restrict__ bsout) {
    int r = blockIdx.x*8 + (threadIdx.x >> 5);
    int lane = threadIdx.x & 31;
    float* p = score + (size_t)r * WX3;
    float v[14];
#pragma unroll
    for (int q = 0; q < 14; q++) {
        int j = q*32 + lane;
        v[q] = (j < WX3) ? p[j] : -INFINITY;
    }
    float m = -INFINITY;
#pragma unroll
    for (int q = 0; q < 14; q++) m = fmaxf(m, v[q]);
#pragma unroll
    for (int o = 16; o > 0; o >>= 1) m = fmaxf(m, __shfl_xor_sync(0xffffffffu, m, o));
    float e[14];
    float s = 0.f;
#pragma unroll
    for (int q = 0; q < 14; q++) { e[q] = __expf(v[q] - m); s += e[q]; }
#pragma unroll
    for (int o = 16; o > 0; o >>= 1) s += __shfl_xor_sync(0xffffffffu, s, o);
    float bs = m + logf(s);
    float rs = 1.f / s;
#pragma unroll
    for (int q = 0; q < 14; q++) {
        int j = q*32 + lane;
        if (j < WX3) p[j] = e[q] * rs;
    }
    if (lane == 0) bsout[r] = bs;
}

// ---------------- ret = score @ y3 via fp16 mma, co-tile 64, 2 blk/SM ------
__global__ __launch_bounds__(288, 2) void k_ret(const float* __restrict__ score) {
    extern __shared__ uint32_t dsm[];
    uint32_t* As2 = dsm;             // [144][k2<24] half2 pairs, pad 28
    uint32_t* Bs2 = dsm + 144*28;    // [64][k2<24], pad 28
    __shared__ int idxs[432];
    int co0 = blockIdx.x*64, win = blockIdx.y, n = blockIdx.z;
    int tid = threadIdx.x, wid = tid >> 5, lane = tid & 31;
    int g = lane >> 2, tig = lane & 3;
    int m0 = wid * 16;
    for (int i = tid; i < 432; i += 288) {
        int seg = i / 144, off = i - seg*144;
        int w2 = (seg == 0) ? win : (seg == 1) ? ((win + 63) & 63) : ((win + 1) & 63);
        idxs[i] = g_idx[n*LTOK + w2*WIN + off];
    }
    float acc[8][4] = {};
    size_t sbase = ((size_t)(n*NWIN + win))*WIN*WX3;
    for (int kc = 0; kc < 9; kc++) {
        __syncthreads();
        for (int i = tid; i < 144*24; i += 288) {
            int r = i / 24, k2 = i - r*24;
            float2 v = *(const float2*)&score[sbase + (size_t)r*WX3 + kc*48 + 2*k2];
            As2[r*28 + k2] = pkh2(v.x, v.y);
        }
        for (int i = tid; i < 64*24; i += 288) {
            int j = i & 63, k2 = i >> 6;
            int tok0 = idxs[kc*48 + 2*k2];
            int tok1 = idxs[kc*48 + 2*k2 + 1];
            float v0 = g_yembed[((size_t)(n*LTOK + tok0))*CIN + co0 + j];
            float v1 = g_yembed[((size_t)(n*LTOK + tok1))*CIN + co0 + j];
            Bs2[j*28 + k2] = pkh2(v0, v1);
        }
        __syncthreads();
#pragma unroll
        for (int ks = 0; ks < 3; ks++) {
            uint32_t a0 = As2[(m0+g  )*28 + ks*8 + tig];
            uint32_t a1 = As2[(m0+g+8)*28 + ks*8 + tig];
            uint32_t a2 = As2[(m0+g  )*28 + ks*8 + tig + 4];
            uint32_t a3 = As2[(m0+g+8)*28 + ks*8 + tig + 4];
#pragma unroll
            for (int t = 0; t < 8; t++) {
                uint32_t b0 = Bs2[(t*8+g)*28 + ks*8 + tig];
                uint32_t b1 = Bs2[(t*8+g)*28 + ks*8 + tig + 4];
                mma16(acc[t], a0, a1, a2, a3, b0, b1);
            }
        }
    }
    int row = win*WIN + m0 + g;
#pragma unroll
    for (int t = 0; t < 8; t++) {
        int col = co0 + t*8 + 2*tig;
        *(float2*)&g_rets[((size_t)(n*LTOK + row    ))*CIN + col] = make_float2(acc[t][0], acc[t][1]);
        *(float2*)&g_rets[((size_t)(n*LTOK + row + 8))*CIN + col] = make_float2(acc[t][2], acc[t][3]);
    }
}

// ---------------- unsort + residual, coalesced via smem transpose ----------
__global__ __launch_bounds__(256) void k_scatter(const float* __restrict__ x,
                                                 float* __restrict__ out) {
    __shared__ float tile[32][257];
    __shared__ int srow[32];
    int n = blockIdx.y, t0 = blockIdx.x * 32, tid = threadIdx.x;
    if (tid < 32) srow[tid] = g_undo[n*LTOK + t0 + tid];
    __syncthreads();
    for (int i = tid; i < 32*64; i += 256) {
        int tt = i >> 6, co4 = (i & 63)*4;
        float4 v = *(const float4*)&g_rets[((size_t)(n*LTOK + srow[tt]))*CIN + co4];
        tile[tt][co4]   = v.x; tile[tt][co4+1] = v.y;
        tile[tt][co4+2] = v.z; tile[tt][co4+3] = v.w;
    }
    __syncthreads();
    for (int i = tid; i < 32*256; i += 256) {
        int co = i >> 5, tt = i & 31;
        size_t gi = ((size_t)(n*CIN + co))*LTOK + t0 + tt;
        out[gi] = tile[tt][co]*0.1f + x[gi];
    }
}

// ---------------- launch ----------------------------------------------------
extern "C" void kernel_launch(void* const* d_in, const int* in_sizes, int n_in,
                              void* d_out, int out_size) {
    const float* x       = (const float*)d_in[0];
    const float* means   = (const float*)d_in[1];
    const float* w_match = (const float*)d_in[2];
    const float* b_match = (const float*)d_in[3];
    const float* w_asm   = (const float*)d_in[4];
    const float* b_asm   = (const float*)d_in[5];
    float* out   = (float*)d_out;
    float* score = out + 18874368;
    float* bs    = out + 50724864;
    float* codes = out + 50798592;

    const int ret_smem = (144*28 + 64*28)*4;   // 23,296 B
    cudaFuncSetAttribute(k_raw, cudaFuncAttributeMaxDynamicSharedMemorySize, 2*144*69*4);
    cudaFuncSetAttribute(k_ret, cudaFuncAttributeMaxDynamicSharedMemorySize, ret_smem);

    k_histzero<<<4, 256>>>();                              // 1
    k_conv3x3<<<dim3(96, 8), 256>>>(x, w_match, b_match);  // 2
    k_histzero<<<4, 256>>>();                              // 3 (filler, idempotent)
    k_conv1x1<<<dim3(72, 4, 8), 256>>>(x, w_asm, b_asm);   // 4 <- profiled
    k_assign<<<dim3(72, 8), 128>>>(means, codes);          // 5
    k_scan<<<8, 32>>>();                                   // 6
    k_place<<<128, 256>>>();                               // 7
    k_raw<<<dim3(64, 3, 8), 256, 2*144*69*4>>>(score);     // 8
    k_lse<<<9216, 256>>>(score, bs);                       // 9
    k_ret<<<dim3(4, 64, 8), 288, ret_smem>>>(score);       // 10
    k_scatter<<<dim3(288, 8), 256>>>(x, out);              // 11
}